// round 5
// baseline (speedup 1.0000x reference)
#include <cuda_runtime.h>
#include <cuda_fp16.h>
#include <cstdint>
#include <cstddef>

#define N_NODES 8192
#define D_FEAT  1024
#define KW      (2 * N_NODES)   // interleaved h/l width in fp16 elements (B only)

#if defined(__CUDA_ARCH_FEAT_SM103_ALL) || defined(__CUDA_ARCH_FEAT_SM100_ALL) || \
    defined(__CUDA_ARCH_FEAT_SM101_ALL) || defined(__CUDA_ARCH_SPECIFIC__) ||     \
    defined(__CUDA_ARCH_FAMILY_SPECIFIC__)
#define HAS_TCG 1
#else
#define HAS_TCG 0
#endif

__device__ const int g_has_tcg = HAS_TCG;

// Scratch (static device globals -- no allocation allowed)
__device__ float  g_dinv[N_NODES];
// B split storage, interleaved per 32-k block: [h[32] | l[32]] fp16
__device__ __half g_B2[(size_t)D_FEAT * KW];    // 33.5 MB

// ---------------------------------------------------------------------------
// Kernel 1: row sums of Mat -> d_inv_sqrt (plain; no conversion pass anymore)
// ---------------------------------------------------------------------------
__global__ void rowsum_kernel(const float* __restrict__ Mat) {
    __shared__ float red[256];
    int row = blockIdx.x;
    const float4* p = reinterpret_cast<const float4*>(Mat + (size_t)row * N_NODES);
    float s = 0.f;
    for (int i = threadIdx.x; i < N_NODES / 4; i += 256) {
        float4 v = p[i];
        s += (v.x + v.y) + (v.z + v.w);
    }
    red[threadIdx.x] = s;
    __syncthreads();
    for (int off = 128; off > 0; off >>= 1) {
        if (threadIdx.x < off) red[threadIdx.x] += red[threadIdx.x + off];
        __syncthreads();
    }
    if (threadIdx.x == 0) g_dinv[row] = rsqrtf(red[0] + 1e-8f);
}

// ---------------------------------------------------------------------------
// Kernel 2: B2[j][k] = split fp16 of (F[k][j] * dinv[k]), interleaved h/l
// ---------------------------------------------------------------------------
__global__ void scale_transpose_kernel(const float* __restrict__ F) {
    __shared__ float tile[32][33];
    int jb = blockIdx.x * 32;
    int kb = blockIdx.y * 32;
    int tx = threadIdx.x;
    for (int r = threadIdx.y; r < 32; r += 8) {
        int k = kb + r;
        tile[r][tx] = F[(size_t)k * D_FEAT + jb + tx] * g_dinv[k];
    }
    __syncthreads();
    for (int r = threadIdx.y; r < 32; r += 8) {
        float a = tile[tx][r];
        __half h = __float2half_rn(a);
        __half l = __float2half_rn(a - __half2float(h));
        size_t base = (size_t)(jb + r) * KW + (size_t)kb * 2;
        g_B2[base + tx]      = h;
        g_B2[base + 32 + tx] = l;
    }
}

// ---------------------------------------------------------------------------
// Kernel 3: 3-pass split-fp16 tcgen05 GEMM with in-loop A conversion
//   out[i][j] = dinv[i] * sum_k (Ah+Al)[i][k] * (Bh+Bl)[j][k]   (drop Al*Bl)
// A is read as fp32 from Mat and split in-kernel (registers -> SMEM).
// CTA tile 256(M) x 256(N), real K per iter = 32 (128B interleaved rows, SW128).
// ---------------------------------------------------------------------------
#define TILE_M 256
#define TILE_N 256
#define TILE_K 32
#define STAGES 3
#define K_ITERS (N_NODES / TILE_K)      // 256

#define A_STAGE_BYTES (TILE_M * 128)    // 32 KB
#define B_STAGE_BYTES (TILE_N * 128)    // 32 KB
#define SMEM_A 0
#define SMEM_B (STAGES * A_STAGE_BYTES)
#define SMEM_CTRL (SMEM_B + STAGES * B_STAGE_BYTES)
#define SMEM_TMEM_PTR (SMEM_CTRL)
#define SMEM_MBAR (SMEM_CTRL + 16)
#define SMEM_TOTAL (SMEM_CTRL + 64 + 1024)

// idesc kind::f16: dtype F32=1@[4], atype F16=0, btype F16=0, N/8@[17], M/16@[24]
#define MMA_IDESC ((1u << 4) | ((TILE_N / 8) << 17) | ((128 / 16) << 24))

__device__ __forceinline__ uint32_t smem_u32(const void* p) {
    uint32_t a;
    asm("{ .reg .u64 t; cvta.to.shared.u64 t, %1; cvt.u32.u64 %0, t; }" : "=r"(a) : "l"(p));
    return a;
}

__device__ __forceinline__ uint32_t elect_one() {
    uint32_t pred;
    asm volatile("{\n\t.reg .pred p;\n\telect.sync _|p, 0xFFFFFFFF;\n\t"
                 "selp.b32 %0, 1, 0, p;\n\t}" : "=r"(pred));
    return pred;
}

__device__ __forceinline__ uint64_t make_desc(uint32_t addr) {
    // SW128, version=1 (Blackwell), SBO=64, LBO=1
    constexpr uint64_t BASE = (uint64_t(2) << 61) | (uint64_t(1) << 46) |
                              (uint64_t(64) << 32) | (uint64_t(1) << 16);
    return BASE | ((uint64_t)(addr >> 4) & 0x3FFF);
}

__device__ __forceinline__ void cpasync16(uint32_t dst, const void* src) {
    asm volatile("cp.async.cg.shared.global [%0], [%1], 16;" :: "r"(dst), "l"(src));
}

__device__ __forceinline__ void sts128(uint32_t addr, uint4 v) {
    asm volatile("st.shared.v4.b32 [%0], {%1, %2, %3, %4};"
                 :: "r"(addr), "r"(v.x), "r"(v.y), "r"(v.z), "r"(v.w));
}

__device__ __forceinline__ void mbar_wait(uint32_t mbar, uint32_t parity) {
    uint32_t done;
    asm volatile("{\n\t.reg .pred p;\n\t"
                 "mbarrier.try_wait.parity.acquire.cta.shared::cta.b64 p, [%1], %2;\n\t"
                 "selp.b32 %0, 1, 0, p;\n\t}"
                 : "=r"(done) : "r"(mbar), "r"(parity) : "memory");
    while (!done) {
        asm volatile("{\n\t.reg .pred p;\n\t"
                     "mbarrier.try_wait.parity.acquire.cta.shared::cta.b64 p, [%1], %2, 0x989680;\n\t"
                     "selp.b32 %0, 1, 0, p;\n\t}"
                     : "=r"(done) : "r"(mbar), "r"(parity) : "memory");
    }
}

__device__ __forceinline__ uint32_t pack_h2(__half a, __half b) {
    __half2 h = __halves2half2(a, b);
    return *reinterpret_cast<uint32_t*>(&h);
}

// Split 8 fp32 (two float4) into high/low fp16 16B chunks.
__device__ __forceinline__ void split8(const float4& a, const float4& b,
                                       uint4& H, uint4& L) {
    float f[8] = {a.x, a.y, a.z, a.w, b.x, b.y, b.z, b.w};
    __half h[8], l[8];
#pragma unroll
    for (int i = 0; i < 8; i++) {
        h[i] = __float2half_rn(f[i]);
        l[i] = __float2half_rn(f[i] - __half2float(h[i]));
    }
    H.x = pack_h2(h[0], h[1]); H.y = pack_h2(h[2], h[3]);
    H.z = pack_h2(h[4], h[5]); H.w = pack_h2(h[6], h[7]);
    L.x = pack_h2(l[0], l[1]); L.y = pack_h2(l[2], l[3]);
    L.z = pack_h2(l[4], l[5]); L.w = pack_h2(l[6], l[7]);
}

#if HAS_TCG
__device__ __forceinline__ void mma_f16(uint32_t d_tmem, uint64_t a_desc, uint64_t b_desc,
                                        uint32_t idesc, uint32_t enable) {
    asm volatile("{\n\t.reg .pred p;\n\tsetp.ne.u32 p, %4, 0;\n\t"
                 "tcgen05.mma.cta_group::1.kind::f16 [%0], %1, %2, %3, {%5, %5, %5, %5}, p;\n\t}"
                 :: "r"(d_tmem), "l"(a_desc), "l"(b_desc), "r"(idesc), "r"(enable), "r"(0u)
                 : "memory");
}

__device__ __forceinline__ void ldtm_x32(uint32_t* r, uint32_t taddr) {
    asm volatile(
        "tcgen05.ld.sync.aligned.32x32b.x32.b32 "
        "{%0, %1, %2, %3, %4, %5, %6, %7, "
        " %8, %9, %10, %11, %12, %13, %14, %15, "
        " %16, %17, %18, %19, %20, %21, %22, %23, "
        " %24, %25, %26, %27, %28, %29, %30, %31}, [%32];"
        : "=r"(r[0]),  "=r"(r[1]),  "=r"(r[2]),  "=r"(r[3]),
          "=r"(r[4]),  "=r"(r[5]),  "=r"(r[6]),  "=r"(r[7]),
          "=r"(r[8]),  "=r"(r[9]),  "=r"(r[10]), "=r"(r[11]),
          "=r"(r[12]), "=r"(r[13]), "=r"(r[14]), "=r"(r[15]),
          "=r"(r[16]), "=r"(r[17]), "=r"(r[18]), "=r"(r[19]),
          "=r"(r[20]), "=r"(r[21]), "=r"(r[22]), "=r"(r[23]),
          "=r"(r[24]), "=r"(r[25]), "=r"(r[26]), "=r"(r[27]),
          "=r"(r[28]), "=r"(r[29]), "=r"(r[30]), "=r"(r[31])
        : "r"(taddr));
}
#endif  // HAS_TCG

// Convert prefetched A fp32 regs (2 rows x 8 float4) into split SMEM stage.
__device__ __forceinline__ void store_A_stage(uint32_t smem_base, int s,
                                              const float4* av, int tid) {
    uint32_t a0 = smem_base + SMEM_A + s * A_STAGE_BYTES;
#pragma unroll
    for (int rr = 0; rr < 2; rr++) {
        int row = tid + rr * 128;
#pragma unroll
        for (int g = 0; g < 4; g++) {
            uint4 H, L;
            split8(av[rr * 8 + g * 2], av[rr * 8 + g * 2 + 1], H, L);
            uint32_t offh = (uint32_t)row * 128 + g * 16;
            uint32_t offl = offh + 64;
            sts128(a0 + (offh ^ ((offh >> 3) & 0x70)), H);
            sts128(a0 + (offl ^ ((offl >> 3) & 0x70)), L);
        }
    }
}

__device__ __forceinline__ void load_A_regs(float4* av, const float* __restrict__ Mat,
                                            int m0, int kiter, int tid) {
    const float4* base = reinterpret_cast<const float4*>(Mat + (size_t)m0 * N_NODES +
                                                         (size_t)kiter * TILE_K);
#pragma unroll
    for (int rr = 0; rr < 2; rr++) {
        int row = tid + rr * 128;
        const float4* src = base + (size_t)row * (N_NODES / 4);
#pragma unroll
        for (int q = 0; q < 8; q++) av[rr * 8 + q] = src[q];
    }
}

__device__ __forceinline__ void load_B_async(uint32_t smem_base, int s, int kiter,
                                             int n0, int tid) {
    uint32_t b0 = smem_base + SMEM_B + s * B_STAGE_BYTES;
    const __half* gB = g_B2 + (size_t)n0 * KW + (size_t)kiter * 64;
#pragma unroll
    for (int i = 0; i < (TILE_N * 8) / 128; i++) {
        int idx = tid + i * 128;
        int row = idx >> 3, c = idx & 7;
        uint32_t off = (uint32_t)row * 128 + c * 16;
        uint32_t sw = off ^ ((off >> 3) & 0x70);
        cpasync16(b0 + sw, gB + (size_t)row * KW + c * 8);
    }
}

__global__ void __launch_bounds__(128, 1)
gcn_gemm_kernel(const float* __restrict__ Mat, float* __restrict__ out) {
#if HAS_TCG
    if (!g_has_tcg) return;
    extern __shared__ char smem[];
    uint32_t smem_base = (smem_u32(smem) + 1023u) & ~1023u;
    int tid = threadIdx.x;
    int wid = tid >> 5;
    int lid = tid & 31;
    int m0 = blockIdx.x * TILE_M;
    int n0 = blockIdx.y * TILE_N;

    if (tid == 0) {
#pragma unroll
        for (int s = 0; s < STAGES; s++) {
            asm volatile("mbarrier.init.shared.b64 [%0], %1;"
                         :: "r"(smem_base + SMEM_MBAR + s * 8), "r"(1u) : "memory");
        }
    }
    if (wid == 0) {
        asm volatile("tcgen05.alloc.cta_group::1.sync.aligned.shared::cta.b32 [%0], %1;"
                     :: "r"(smem_base + SMEM_TMEM_PTR), "r"(512u) : "memory");
    }
    __syncthreads();

    uint32_t tb;
    asm volatile("ld.shared.b32 %0, [%1];" : "=r"(tb) : "r"(smem_base + SMEM_TMEM_PTR));

    // Prologue: fill stages 0 .. STAGES-2 (A synchronous convert, B async)
#pragma unroll
    for (int p = 0; p < STAGES - 1; p++) {
        float4 av[16];
        load_A_regs(av, Mat, m0, p, tid);
        store_A_stage(smem_base, p, av, tid);
        load_B_async(smem_base, p, p, n0, tid);
        asm volatile("cp.async.commit_group;" ::: "memory");
    }

    for (int k = 0; k < K_ITERS; k++) {
        int s = k % STAGES;
        int kn = k + STAGES - 1;
        bool pf = (kn < K_ITERS);

        // Prefetch A fp32 for stage kn into registers (hidden under MMA pace)
        float4 av[16];
        if (pf) load_A_regs(av, Mat, m0, kn, tid);

        if (k == K_ITERS - 1) {
            asm volatile("cp.async.wait_group 0;" ::: "memory");
        } else {
            asm volatile("cp.async.wait_group 1;" ::: "memory");
        }
        __syncthreads();

        if (wid == 0) {
            if (elect_one()) {
                asm volatile("fence.proxy.async.shared::cta;" ::: "memory");
                uint32_t a_base = smem_base + SMEM_A + s * A_STAGE_BYTES;
                uint32_t b_base = smem_base + SMEM_B + s * B_STAGE_BYTES;
                uint64_t ah0 = make_desc(a_base);             // M-half 0
                uint64_t ah1 = make_desc(a_base + 128 * 128); // M-half 1
                uint64_t bh  = make_desc(b_base);
#pragma unroll
                for (int ks = 0; ks < 2; ks++) {   // two K=16 chunks of real K=32
                    uint32_t en0 = (k > 0 || ks > 0) ? 1u : 0u;
                    uint64_t dh = 2 * ks;          // h chunk offset (16B units)
                    uint64_t dl = 4 + 2 * ks;      // l chunk offset
                    mma_f16(tb,       ah0 + dh, bh + dh, MMA_IDESC, en0);  // Ah*Bh
                    mma_f16(tb + 256, ah1 + dh, bh + dh, MMA_IDESC, en0);
                    mma_f16(tb,       ah0 + dh, bh + dl, MMA_IDESC, 1u);  // Ah*Bl
                    mma_f16(tb + 256, ah1 + dh, bh + dl, MMA_IDESC, 1u);
                    mma_f16(tb,       ah0 + dl, bh + dh, MMA_IDESC, 1u);  // Al*Bh
                    mma_f16(tb + 256, ah1 + dl, bh + dh, MMA_IDESC, 1u);
                }
                asm volatile(
                    "tcgen05.commit.cta_group::1.mbarrier::arrive::one.shared::cluster.b64 [%0];"
                    :: "r"(smem_base + SMEM_MBAR + s * 8) : "memory");
            }
        }

        if (pf) {
            if (k > 0) {
                int t = (k - 1) % STAGES;   // == kn % STAGES; wait MMA of iter k-1
                uint32_t par = (uint32_t)(((k - 1) / STAGES) & 1);
                mbar_wait(smem_base + SMEM_MBAR + t * 8, par);
            }
            store_A_stage(smem_base, kn % STAGES, av, tid);
            load_B_async(smem_base, kn % STAGES, kn, n0, tid);
            asm volatile("cp.async.commit_group;" ::: "memory");
        }
    }

    {
        int t = (K_ITERS - 1) % STAGES;
        uint32_t par = (uint32_t)(((K_ITERS - 1) / STAGES) & 1);
        mbar_wait(smem_base + SMEM_MBAR + t * 8, par);
    }
    asm volatile("tcgen05.fence::after_thread_sync;" ::: "memory");

    // Epilogue: TMEM -> regs, scale by dinv[row], store fp32
#pragma unroll
    for (int mh = 0; mh < 2; mh++) {
        int row = m0 + mh * 128 + wid * 32 + lid;
        float ds = g_dinv[row];
        float* orow = out + (size_t)row * D_FEAT + n0;
#pragma unroll
        for (int c = 0; c < 8; c++) {
            uint32_t r[32];
            ldtm_x32(r, tb + mh * 256 + c * 32);
            asm volatile("tcgen05.wait::ld.sync.aligned;" ::: "memory");
#pragma unroll
            for (int q = 0; q < 8; q++) {
                float4 v;
                v.x = __uint_as_float(r[q * 4 + 0]) * ds;
                v.y = __uint_as_float(r[q * 4 + 1]) * ds;
                v.z = __uint_as_float(r[q * 4 + 2]) * ds;
                v.w = __uint_as_float(r[q * 4 + 3]) * ds;
                *reinterpret_cast<float4*>(orow + c * 32 + q * 4) = v;
            }
        }
    }

    __syncthreads();
    if (wid == 0) {
        asm volatile("tcgen05.relinquish_alloc_permit.cta_group::1.sync.aligned;" ::: "memory");
        asm volatile("tcgen05.dealloc.cta_group::1.sync.aligned.b32 %0, %1;"
                     :: "r"(tb), "r"(512u));
    }
#endif  // HAS_TCG
}

// ---------------------------------------------------------------------------
// FFMA fallback GEMM (only runs if the live device image has no tcgen05).
// Reads original fp32 inputs directly -- fully independent correctness path.
// ---------------------------------------------------------------------------
__global__ void __launch_bounds__(256)
gcn_gemm_fallback(const float* __restrict__ Mat, const float* __restrict__ F,
                  float* __restrict__ out) {
    if (g_has_tcg) return;
    __shared__ float As[16][132];
    __shared__ float Bs[16][132];
    int m0 = blockIdx.x * 128;
    int n0 = blockIdx.y * 128;
    int tx = threadIdx.x & 15;
    int ty = threadIdx.x >> 4;
    float acc[8][8];
#pragma unroll
    for (int i = 0; i < 8; i++)
#pragma unroll
        for (int j = 0; j < 8; j++) acc[i][j] = 0.f;

    for (int kk = 0; kk < N_NODES; kk += 16) {
        for (int i = threadIdx.x; i < 128 * 16; i += 256) {
            int r = i >> 4, c = i & 15;
            As[c][r] = Mat[(size_t)(m0 + r) * N_NODES + kk + c];
            Bs[c][r] = F[(size_t)(kk + c) * D_FEAT + n0 + r] * g_dinv[kk + c];
        }
        __syncthreads();
#pragma unroll
        for (int c = 0; c < 16; c++) {
            float a[8], b[8];
#pragma unroll
            for (int i = 0; i < 8; i++) a[i] = As[c][ty * 8 + i];
#pragma unroll
            for (int j = 0; j < 8; j++) b[j] = Bs[c][tx * 8 + j];
#pragma unroll
            for (int i = 0; i < 8; i++)
#pragma unroll
                for (int j = 0; j < 8; j++) acc[i][j] += a[i] * b[j];
        }
        __syncthreads();
    }
#pragma unroll
    for (int i = 0; i < 8; i++) {
        int m = m0 + ty * 8 + i;
        float ds = g_dinv[m];
#pragma unroll
        for (int j = 0; j < 8; j++)
            out[(size_t)m * D_FEAT + n0 + tx * 8 + j] = acc[i][j] * ds;
    }
}

// ---------------------------------------------------------------------------
extern "C" void kernel_launch(void* const* d_in, const int* in_sizes, int n_in,
                              void* d_out, int out_size) {
    const float* features = (const float*)d_in[0];
    const float* Mat = (const float*)d_in[1];
    float* out = (float*)d_out;

    rowsum_kernel<<<N_NODES, 256>>>(Mat);

    dim3 tpose_block(32, 8);
    dim3 tpose_grid(D_FEAT / 32, N_NODES / 32);
    scale_transpose_kernel<<<tpose_grid, tpose_block>>>(features);

    cudaFuncSetAttribute(gcn_gemm_kernel, cudaFuncAttributeMaxDynamicSharedMemorySize, SMEM_TOTAL);
    dim3 gemm_grid(N_NODES / TILE_M, D_FEAT / TILE_N);
    gcn_gemm_kernel<<<gemm_grid, 128, SMEM_TOTAL>>>(Mat, out);

    dim3 fb_grid(N_NODES / 128, D_FEAT / 128);
    gcn_gemm_fallback<<<fb_grid, 256>>>(Mat, features, out);
}

// round 6
// speedup vs baseline: 1.3904x; 1.3904x over previous
#include <cuda_runtime.h>
#include <cuda_fp16.h>
#include <cstdint>
#include <cstddef>

#define N_NODES 8192
#define D_FEAT  1024
#define KW      (2 * N_NODES)   // interleaved h/l width in fp16 elements

#if defined(__CUDA_ARCH_FEAT_SM103_ALL) || defined(__CUDA_ARCH_FEAT_SM100_ALL) || \
    defined(__CUDA_ARCH_FEAT_SM101_ALL) || defined(__CUDA_ARCH_SPECIFIC__) ||     \
    defined(__CUDA_ARCH_FAMILY_SPECIFIC__)
#define HAS_TCG 1
#else
#define HAS_TCG 0
#endif

__device__ const int g_has_tcg = HAS_TCG;

// Scratch (static device globals -- no allocation allowed)
__device__ float  g_dinv[N_NODES];
// Interleaved split storage: row r, k-block b (32 k each):
//   [r*KW + b*64 + 0..31] = h(val[k]), [r*KW + b*64 + 32..63] = l(val[k])
__device__ __half g_A2[(size_t)N_NODES * KW];   // 268 MB, split fp16 of Mat
__device__ __half g_B2[(size_t)D_FEAT * KW];    // 33.5 MB, split fp16 of G^T (G=dinv*F)

__device__ __forceinline__ uint32_t pack_h2(__half a, __half b) {
    __half2 h = __halves2half2(a, b);
    return *reinterpret_cast<uint32_t*>(&h);
}

// ---------------------------------------------------------------------------
// Kernel 1: fused row sums + fp16 h/l split of Mat (interleaved, 16B stores)
// ---------------------------------------------------------------------------
__global__ void rowsum_convert_kernel(const float* __restrict__ Mat) {
    __shared__ float red[256];
    int row = blockIdx.x;
    const float4* p = reinterpret_cast<const float4*>(Mat + (size_t)row * N_NODES);
    __half* dst = g_A2 + (size_t)row * KW;
    float s = 0.f;
    // 8 elements per thread per iter -> one 16B h store + one 16B l store
    for (int i = threadIdx.x; i < N_NODES / 8; i += 256) {
        float4 v0 = p[i * 2];
        float4 v1 = p[i * 2 + 1];
        s += (v0.x + v0.y) + (v0.z + v0.w) + (v1.x + v1.y) + (v1.z + v1.w);
        float f[8] = {v0.x, v0.y, v0.z, v0.w, v1.x, v1.y, v1.z, v1.w};
        __half h[8], l[8];
#pragma unroll
        for (int q = 0; q < 8; q++) {
            h[q] = __float2half_rn(f[q]);
            l[q] = __float2half_rn(f[q] - __half2float(h[q]));
        }
        uint4 H, L;
        H.x = pack_h2(h[0], h[1]); H.y = pack_h2(h[2], h[3]);
        H.z = pack_h2(h[4], h[5]); H.w = pack_h2(h[6], h[7]);
        L.x = pack_h2(l[0], l[1]); L.y = pack_h2(l[2], l[3]);
        L.z = pack_h2(l[4], l[5]); L.w = pack_h2(l[6], l[7]);
        int k = i * 8;
        int blk = k >> 5, pos = k & 31;                  // pos in {0,8,16,24}
        *reinterpret_cast<uint4*>(dst + blk * 64 + pos)      = H;
        *reinterpret_cast<uint4*>(dst + blk * 64 + 32 + pos) = L;
    }
    red[threadIdx.x] = s;
    __syncthreads();
    for (int off = 128; off > 0; off >>= 1) {
        if (threadIdx.x < off) red[threadIdx.x] += red[threadIdx.x + off];
        __syncthreads();
    }
    if (threadIdx.x == 0) g_dinv[row] = rsqrtf(red[0] + 1e-8f);
}

// ---------------------------------------------------------------------------
// Kernel 2: B2[j][k] = split fp16 of (F[k][j] * dinv[k]), interleaved h/l
// ---------------------------------------------------------------------------
__global__ void scale_transpose_kernel(const float* __restrict__ F) {
    __shared__ float tile[32][33];
    int jb = blockIdx.x * 32;
    int kb = blockIdx.y * 32;
    int tx = threadIdx.x;
    for (int r = threadIdx.y; r < 32; r += 8) {
        int k = kb + r;
        tile[r][tx] = F[(size_t)k * D_FEAT + jb + tx] * g_dinv[k];
    }
    __syncthreads();
    for (int r = threadIdx.y; r < 32; r += 8) {
        float a = tile[tx][r];
        __half h = __float2half_rn(a);
        __half l = __float2half_rn(a - __half2float(h));
        size_t base = (size_t)(jb + r) * KW + (size_t)kb * 2;
        g_B2[base + tx]      = h;
        g_B2[base + 32 + tx] = l;
    }
}

// ---------------------------------------------------------------------------
// Kernel 3: 3-pass split-fp16 tcgen05 GEMM
//   out[i][j] = dinv[i] * sum_k (Ah+Al)[i][k] * (Bh+Bl)[j][k]   (drop Al*Bl)
// CTA tile 256(M) x 256(N), real K per iter = 32 (128B interleaved rows, SW128).
// ---------------------------------------------------------------------------
#define TILE_M 256
#define TILE_N 256
#define TILE_K 32
#define STAGES 3
#define K_ITERS (N_NODES / TILE_K)      // 256

#define A_STAGE_BYTES (TILE_M * 128)    // 32 KB
#define B_STAGE_BYTES (TILE_N * 128)    // 32 KB
#define SMEM_A 0
#define SMEM_B (STAGES * A_STAGE_BYTES)
#define SMEM_CTRL (SMEM_B + STAGES * B_STAGE_BYTES)
#define SMEM_TMEM_PTR (SMEM_CTRL)
#define SMEM_MBAR (SMEM_CTRL + 16)
#define SMEM_TOTAL (SMEM_CTRL + 64 + 1024)

// idesc kind::f16: dtype F32=1@[4], atype F16=0, btype F16=0, N/8@[17], M/16@[24]
#define MMA_IDESC ((1u << 4) | ((TILE_N / 8) << 17) | ((128 / 16) << 24))

__device__ __forceinline__ uint32_t smem_u32(const void* p) {
    uint32_t a;
    asm("{ .reg .u64 t; cvta.to.shared.u64 t, %1; cvt.u32.u64 %0, t; }" : "=r"(a) : "l"(p));
    return a;
}

__device__ __forceinline__ uint32_t elect_one() {
    uint32_t pred;
    asm volatile("{\n\t.reg .pred p;\n\telect.sync _|p, 0xFFFFFFFF;\n\t"
                 "selp.b32 %0, 1, 0, p;\n\t}" : "=r"(pred));
    return pred;
}

__device__ __forceinline__ uint64_t make_desc(uint32_t addr) {
    // SW128, version=1 (Blackwell), SBO=64, LBO=1
    constexpr uint64_t BASE = (uint64_t(2) << 61) | (uint64_t(1) << 46) |
                              (uint64_t(64) << 32) | (uint64_t(1) << 16);
    return BASE | ((uint64_t)(addr >> 4) & 0x3FFF);
}

__device__ __forceinline__ void cpasync16(uint32_t dst, const void* src) {
    asm volatile("cp.async.cg.shared.global [%0], [%1], 16;" :: "r"(dst), "l"(src));
}

__device__ __forceinline__ void mbar_wait(uint32_t mbar, uint32_t parity) {
    uint32_t done;
    asm volatile("{\n\t.reg .pred p;\n\t"
                 "mbarrier.try_wait.parity.acquire.cta.shared::cta.b64 p, [%1], %2;\n\t"
                 "selp.b32 %0, 1, 0, p;\n\t}"
                 : "=r"(done) : "r"(mbar), "r"(parity) : "memory");
    while (!done) {
        asm volatile("{\n\t.reg .pred p;\n\t"
                     "mbarrier.try_wait.parity.acquire.cta.shared::cta.b64 p, [%1], %2, 0x989680;\n\t"
                     "selp.b32 %0, 1, 0, p;\n\t}"
                     : "=r"(done) : "r"(mbar), "r"(parity) : "memory");
    }
}

#if HAS_TCG
__device__ __forceinline__ void mma_f16(uint32_t d_tmem, uint64_t a_desc, uint64_t b_desc,
                                        uint32_t idesc, uint32_t enable) {
    asm volatile("{\n\t.reg .pred p;\n\tsetp.ne.u32 p, %4, 0;\n\t"
                 "tcgen05.mma.cta_group::1.kind::f16 [%0], %1, %2, %3, {%5, %5, %5, %5}, p;\n\t}"
                 :: "r"(d_tmem), "l"(a_desc), "l"(b_desc), "r"(idesc), "r"(enable), "r"(0u)
                 : "memory");
}

__device__ __forceinline__ void ldtm_x32(uint32_t* r, uint32_t taddr) {
    asm volatile(
        "tcgen05.ld.sync.aligned.32x32b.x32.b32 "
        "{%0, %1, %2, %3, %4, %5, %6, %7, "
        " %8, %9, %10, %11, %12, %13, %14, %15, "
        " %16, %17, %18, %19, %20, %21, %22, %23, "
        " %24, %25, %26, %27, %28, %29, %30, %31}, [%32];"
        : "=r"(r[0]),  "=r"(r[1]),  "=r"(r[2]),  "=r"(r[3]),
          "=r"(r[4]),  "=r"(r[5]),  "=r"(r[6]),  "=r"(r[7]),
          "=r"(r[8]),  "=r"(r[9]),  "=r"(r[10]), "=r"(r[11]),
          "=r"(r[12]), "=r"(r[13]), "=r"(r[14]), "=r"(r[15]),
          "=r"(r[16]), "=r"(r[17]), "=r"(r[18]), "=r"(r[19]),
          "=r"(r[20]), "=r"(r[21]), "=r"(r[22]), "=r"(r[23]),
          "=r"(r[24]), "=r"(r[25]), "=r"(r[26]), "=r"(r[27]),
          "=r"(r[28]), "=r"(r[29]), "=r"(r[30]), "=r"(r[31])
        : "r"(taddr));
}
#endif  // HAS_TCG

// Load one stage: A tile 256x128B, B tile 256x128B from interleaved arrays.
__device__ __forceinline__ void load_stage(uint32_t smem_base, int s, int kiter,
                                           int m0, int n0, int tid) {
    uint32_t a0 = smem_base + SMEM_A + s * A_STAGE_BYTES;
    uint32_t b0 = smem_base + SMEM_B + s * B_STAGE_BYTES;
    const __half* gA = g_A2 + (size_t)m0 * KW + (size_t)kiter * 64;
    const __half* gB = g_B2 + (size_t)n0 * KW + (size_t)kiter * 64;
#pragma unroll
    for (int i = 0; i < (TILE_M * 8) / 128; i++) {
        int idx = tid + i * 128;
        int row = idx >> 3, c = idx & 7;
        uint32_t off = (uint32_t)row * 128 + c * 16;
        uint32_t sw = off ^ ((off >> 3) & 0x70);
        cpasync16(a0 + sw, gA + (size_t)row * KW + c * 8);
    }
#pragma unroll
    for (int i = 0; i < (TILE_N * 8) / 128; i++) {
        int idx = tid + i * 128;
        int row = idx >> 3, c = idx & 7;
        uint32_t off = (uint32_t)row * 128 + c * 16;
        uint32_t sw = off ^ ((off >> 3) & 0x70);
        cpasync16(b0 + sw, gB + (size_t)row * KW + c * 8);
    }
}

__global__ void __launch_bounds__(128, 1)
gcn_gemm_kernel(float* __restrict__ out) {
#if HAS_TCG
    if (!g_has_tcg) return;
    extern __shared__ char smem[];
    uint32_t smem_base = (smem_u32(smem) + 1023u) & ~1023u;
    int tid = threadIdx.x;
    int wid = tid >> 5;
    int lid = tid & 31;
    int m0 = blockIdx.x * TILE_M;
    int n0 = blockIdx.y * TILE_N;

    if (tid == 0) {
#pragma unroll
        for (int s = 0; s < STAGES; s++) {
            asm volatile("mbarrier.init.shared.b64 [%0], %1;"
                         :: "r"(smem_base + SMEM_MBAR + s * 8), "r"(1u) : "memory");
        }
    }
    if (wid == 0) {
        asm volatile("tcgen05.alloc.cta_group::1.sync.aligned.shared::cta.b32 [%0], %1;"
                     :: "r"(smem_base + SMEM_TMEM_PTR), "r"(512u) : "memory");
    }
    __syncthreads();

    uint32_t tb;
    asm volatile("ld.shared.b32 %0, [%1];" : "=r"(tb) : "r"(smem_base + SMEM_TMEM_PTR));

#pragma unroll
    for (int p = 0; p < STAGES - 1; p++) {
        load_stage(smem_base, p, p, m0, n0, tid);
        asm volatile("cp.async.commit_group;" ::: "memory");
    }

    for (int k = 0; k < K_ITERS; k++) {
        int s = k % STAGES;
        if (k == K_ITERS - 1) {
            asm volatile("cp.async.wait_group 0;" ::: "memory");
        } else {
            asm volatile("cp.async.wait_group 1;" ::: "memory");
        }
        __syncthreads();

        if (wid == 0) {
            if (elect_one()) {
                asm volatile("fence.proxy.async.shared::cta;" ::: "memory");
                uint32_t a_base = smem_base + SMEM_A + s * A_STAGE_BYTES;
                uint32_t b_base = smem_base + SMEM_B + s * B_STAGE_BYTES;
                uint64_t ah0 = make_desc(a_base);             // M-half 0
                uint64_t ah1 = make_desc(a_base + 128 * 128); // M-half 1
                uint64_t bh  = make_desc(b_base);
#pragma unroll
                for (int ks = 0; ks < 2; ks++) {   // two K=16 chunks of real K=32
                    uint32_t en0 = (k > 0 || ks > 0) ? 1u : 0u;
                    uint64_t dh = 2 * ks;          // h chunk offset (16B units)
                    uint64_t dl = 4 + 2 * ks;      // l chunk offset
                    mma_f16(tb,       ah0 + dh, bh + dh, MMA_IDESC, en0);  // Ah*Bh
                    mma_f16(tb + 256, ah1 + dh, bh + dh, MMA_IDESC, en0);
                    mma_f16(tb,       ah0 + dh, bh + dl, MMA_IDESC, 1u);  // Ah*Bl
                    mma_f16(tb + 256, ah1 + dh, bh + dl, MMA_IDESC, 1u);
                    mma_f16(tb,       ah0 + dl, bh + dh, MMA_IDESC, 1u);  // Al*Bh
                    mma_f16(tb + 256, ah1 + dl, bh + dh, MMA_IDESC, 1u);
                }
                asm volatile(
                    "tcgen05.commit.cta_group::1.mbarrier::arrive::one.shared::cluster.b64 [%0];"
                    :: "r"(smem_base + SMEM_MBAR + s * 8) : "memory");
            }
        }

        int kn = k + STAGES - 1;
        if (kn < K_ITERS) {
            if (k > 0) {
                int t = (k - 1) % STAGES;   // stage to refill; wait MMA of iter k-1
                uint32_t par = (uint32_t)(((k - 1) / STAGES) & 1);
                mbar_wait(smem_base + SMEM_MBAR + t * 8, par);
            }
            load_stage(smem_base, kn % STAGES, kn, m0, n0, tid);
            asm volatile("cp.async.commit_group;" ::: "memory");
        }
    }

    {
        int t = (K_ITERS - 1) % STAGES;
        uint32_t par = (uint32_t)(((K_ITERS - 1) / STAGES) & 1);
        mbar_wait(smem_base + SMEM_MBAR + t * 8, par);
    }
    asm volatile("tcgen05.fence::after_thread_sync;" ::: "memory");

    // Epilogue: TMEM -> regs, scale by dinv[row], store fp32
#pragma unroll
    for (int mh = 0; mh < 2; mh++) {
        int row = m0 + mh * 128 + wid * 32 + lid;
        float ds = g_dinv[row];
        float* orow = out + (size_t)row * D_FEAT + n0;
#pragma unroll
        for (int c = 0; c < 8; c++) {
            uint32_t r[32];
            ldtm_x32(r, tb + mh * 256 + c * 32);
            asm volatile("tcgen05.wait::ld.sync.aligned;" ::: "memory");
#pragma unroll
            for (int q = 0; q < 8; q++) {
                float4 v;
                v.x = __uint_as_float(r[q * 4 + 0]) * ds;
                v.y = __uint_as_float(r[q * 4 + 1]) * ds;
                v.z = __uint_as_float(r[q * 4 + 2]) * ds;
                v.w = __uint_as_float(r[q * 4 + 3]) * ds;
                *reinterpret_cast<float4*>(orow + c * 32 + q * 4) = v;
            }
        }
    }

    __syncthreads();
    if (wid == 0) {
        asm volatile("tcgen05.relinquish_alloc_permit.cta_group::1.sync.aligned;" ::: "memory");
        asm volatile("tcgen05.dealloc.cta_group::1.sync.aligned.b32 %0, %1;"
                     :: "r"(tb), "r"(512u));
    }
#endif  // HAS_TCG
}

// ---------------------------------------------------------------------------
// FFMA fallback GEMM (only runs if the live device image has no tcgen05).
// ---------------------------------------------------------------------------
__global__ void __launch_bounds__(256)
gcn_gemm_fallback(const float* __restrict__ Mat, const float* __restrict__ F,
                  float* __restrict__ out) {
    if (g_has_tcg) return;
    __shared__ float As[16][132];
    __shared__ float Bs[16][132];
    int m0 = blockIdx.x * 128;
    int n0 = blockIdx.y * 128;
    int tx = threadIdx.x & 15;
    int ty = threadIdx.x >> 4;
    float acc[8][8];
#pragma unroll
    for (int i = 0; i < 8; i++)
#pragma unroll
        for (int j = 0; j < 8; j++) acc[i][j] = 0.f;

    for (int kk = 0; kk < N_NODES; kk += 16) {
        for (int i = threadIdx.x; i < 128 * 16; i += 256) {
            int r = i >> 4, c = i & 15;
            As[c][r] = Mat[(size_t)(m0 + r) * N_NODES + kk + c];
            Bs[c][r] = F[(size_t)(kk + c) * D_FEAT + n0 + r] * g_dinv[kk + c];
        }
        __syncthreads();
#pragma unroll
        for (int c = 0; c < 16; c++) {
            float a[8], b[8];
#pragma unroll
            for (int i = 0; i < 8; i++) a[i] = As[c][ty * 8 + i];
#pragma unroll
            for (int j = 0; j < 8; j++) b[j] = Bs[c][tx * 8 + j];
#pragma unroll
            for (int i = 0; i < 8; i++)
#pragma unroll
                for (int j = 0; j < 8; j++) acc[i][j] += a[i] * b[j];
        }
        __syncthreads();
    }
#pragma unroll
    for (int i = 0; i < 8; i++) {
        int m = m0 + ty * 8 + i;
        float ds = g_dinv[m];
#pragma unroll
        for (int j = 0; j < 8; j++)
            out[(size_t)m * D_FEAT + n0 + tx * 8 + j] = acc[i][j] * ds;
    }
}

// ---------------------------------------------------------------------------
extern "C" void kernel_launch(void* const* d_in, const int* in_sizes, int n_in,
                              void* d_out, int out_size) {
    const float* features = (const float*)d_in[0];
    const float* Mat = (const float*)d_in[1];
    float* out = (float*)d_out;

    rowsum_convert_kernel<<<N_NODES, 256>>>(Mat);

    dim3 tpose_block(32, 8);
    dim3 tpose_grid(D_FEAT / 32, N_NODES / 32);
    scale_transpose_kernel<<<tpose_grid, tpose_block>>>(features);

    cudaFuncSetAttribute(gcn_gemm_kernel, cudaFuncAttributeMaxDynamicSharedMemorySize, SMEM_TOTAL);
    dim3 gemm_grid(N_NODES / TILE_M, D_FEAT / TILE_N);
    gcn_gemm_kernel<<<gemm_grid, 128, SMEM_TOTAL>>>(out);

    dim3 fb_grid(N_NODES / 128, D_FEAT / 128);
    gcn_gemm_fallback<<<fb_grid, 256>>>(Mat, features, out);
}

// round 7
// speedup vs baseline: 1.6808x; 1.2089x over previous
#include <cuda_runtime.h>
#include <cuda_fp16.h>
#include <cuda_fp8.h>
#include <cstdint>
#include <cstddef>

#define N_NODES 8192
#define D_FEAT  1024
#define ROW_BYTES 32768   // per row: 256 blocks x 128B ( [h 64B | e4m3 32B | e5m2 32B] per 32-k )

#if defined(__CUDA_ARCH_FEAT_SM103_ALL) || defined(__CUDA_ARCH_FEAT_SM100_ALL) || \
    defined(__CUDA_ARCH_FEAT_SM101_ALL) || defined(__CUDA_ARCH_SPECIFIC__) ||     \
    defined(__CUDA_ARCH_FAMILY_SPECIFIC__)
#define HAS_TCG 1
#else
#define HAS_TCG 0
#endif

__device__ const int g_has_tcg = HAS_TCG;

// Scratch (static device globals -- no allocation allowed)
__device__ float   g_dinv[N_NODES];
__device__ uint8_t g_A2[(size_t)N_NODES * ROW_BYTES];  // 268 MB: A split (h16 / e4m3 / e5m2)
__device__ uint8_t g_B2[(size_t)D_FEAT * ROW_BYTES];   // 33.5 MB: (64*G)^T split

__device__ __forceinline__ uint32_t pack_h2(__half a, __half b) {
    __half2 h = __halves2half2(a, b);
    return *reinterpret_cast<uint32_t*>(&h);
}
__device__ __forceinline__ uint8_t f2e4m3(float f) {
    return (uint8_t)__nv_cvt_float_to_fp8(f, __NV_SATFINITE, __NV_E4M3);
}
__device__ __forceinline__ uint8_t f2e5m2(float f) {
    return (uint8_t)__nv_cvt_float_to_fp8(f, __NV_SATFINITE, __NV_E5M2);
}

// ---------------------------------------------------------------------------
// Kernel 1: fused row sums + A split (fp16 high, e4m3 full, e5m2 residual)
// ---------------------------------------------------------------------------
__global__ void rowsum_convert_kernel(const float* __restrict__ Mat) {
    __shared__ float red[256];
    int row = blockIdx.x;
    const float4* p = reinterpret_cast<const float4*>(Mat + (size_t)row * N_NODES);
    uint8_t* dst = g_A2 + (size_t)row * ROW_BYTES;
    float s = 0.f;
    for (int i = threadIdx.x; i < N_NODES / 8; i += 256) {
        float4 v0 = p[i * 2];
        float4 v1 = p[i * 2 + 1];
        s += (v0.x + v0.y) + (v0.z + v0.w) + (v1.x + v1.y) + (v1.z + v1.w);
        float f[8] = {v0.x, v0.y, v0.z, v0.w, v1.x, v1.y, v1.z, v1.w};
        __half h[8];
        uint64_t pa = 0, pl = 0;
#pragma unroll
        for (int q = 0; q < 8; q++) {
            h[q] = __float2half_rn(f[q]);
            pa |= (uint64_t)f2e4m3(f[q]) << (8 * q);
            pl |= (uint64_t)f2e5m2(f[q] - __half2float(h[q])) << (8 * q);
        }
        uint4 H;
        H.x = pack_h2(h[0], h[1]); H.y = pack_h2(h[2], h[3]);
        H.z = pack_h2(h[4], h[5]); H.w = pack_h2(h[6], h[7]);
        int k = i * 8;
        int blk = k >> 5, pos = k & 31;                 // pos in {0,8,16,24}
        uint8_t* b = dst + (size_t)blk * 128;
        *reinterpret_cast<uint4*>(b + pos * 2) = H;
        *reinterpret_cast<uint64_t*>(b + 64 + pos) = pa;
        *reinterpret_cast<uint64_t*>(b + 96 + pos) = pl;
    }
    red[threadIdx.x] = s;
    __syncthreads();
    for (int off = 128; off > 0; off >>= 1) {
        if (threadIdx.x < off) red[threadIdx.x] += red[threadIdx.x + off];
        __syncthreads();
    }
    if (threadIdx.x == 0) g_dinv[row] = rsqrtf(red[0] + 1e-8f);
}

// ---------------------------------------------------------------------------
// Kernel 2: B2[j] = split of (64 * F[k][j] * dinv[k])^T  (h16 / e4m3 / e5m2)
// ---------------------------------------------------------------------------
__global__ void scale_transpose_kernel(const float* __restrict__ F) {
    __shared__ float tile[32][33];
    int jb = blockIdx.x * 32;
    int kb = blockIdx.y * 32;
    int tx = threadIdx.x;
    for (int r = threadIdx.y; r < 32; r += 8) {
        int k = kb + r;
        tile[r][tx] = F[(size_t)k * D_FEAT + jb + tx] * g_dinv[k];
    }
    __syncthreads();
    for (int r = threadIdx.y; r < 32; r += 8) {
        float a = tile[tx][r] * 64.0f;   // pre-scale so residuals stay in e5m2 range
        __half h = __float2half_rn(a);
        uint8_t* b = g_B2 + (size_t)(jb + r) * ROW_BYTES + (size_t)(kb >> 5) * 128;
        *reinterpret_cast<__half*>(b + tx * 2) = h;
        b[64 + tx] = f2e4m3(a);
        b[96 + tx] = f2e5m2(a - __half2float(h));
    }
}

// ---------------------------------------------------------------------------
// Kernel 3: mixed fp16/fp8 3-pass tcgen05 GEMM
//   acc = Ah@Gh (f16) + A8@Gl8 (e4m3 x e5m2) + Al8@G8 (e5m2 x e4m3)
//   out[i][j] = dinv[i] * 2^-6 * acc
// CTA tile 256(M) x 256(N), real K per iter = 32 (128B rows, SW128), 3 stages.
// ---------------------------------------------------------------------------
#define TILE_M 256
#define TILE_N 256
#define TILE_K 32
#define STAGES 3
#define K_ITERS (N_NODES / TILE_K)      // 256

#define A_STAGE_BYTES (TILE_M * 128)    // 32 KB
#define B_STAGE_BYTES (TILE_N * 128)    // 32 KB
#define SMEM_A 0
#define SMEM_B (STAGES * A_STAGE_BYTES)
#define SMEM_CTRL (SMEM_B + STAGES * B_STAGE_BYTES)
#define SMEM_TMEM_PTR (SMEM_CTRL)
#define SMEM_MBAR (SMEM_CTRL + 16)
#define SMEM_TOTAL (SMEM_CTRL + 64 + 1024)

// Unified idesc layout: cformat F32=1@[4:6), aformat@[7:10), bformat@[10:13),
// N/8@[17:23), M/16@[24:29).  fp16: fmt 0.  fp8: e4m3=0, e5m2=1.
#define IDESC_F16 ((1u << 4) | ((TILE_N / 8) << 17) | ((128 / 16) << 24))
#define IDESC_F8(AT, BT) ((1u << 4) | ((AT) << 7) | ((BT) << 10) | ((TILE_N / 8) << 17) | ((128 / 16) << 24))

__device__ __forceinline__ uint32_t smem_u32(const void* p) {
    uint32_t a;
    asm("{ .reg .u64 t; cvta.to.shared.u64 t, %1; cvt.u32.u64 %0, t; }" : "=r"(a) : "l"(p));
    return a;
}

__device__ __forceinline__ uint32_t elect_one() {
    uint32_t pred;
    asm volatile("{\n\t.reg .pred p;\n\telect.sync _|p, 0xFFFFFFFF;\n\t"
                 "selp.b32 %0, 1, 0, p;\n\t}" : "=r"(pred));
    return pred;
}

__device__ __forceinline__ uint64_t make_desc(uint32_t addr) {
    // SW128, version=1 (Blackwell), SBO=64, LBO=1
    constexpr uint64_t BASE = (uint64_t(2) << 61) | (uint64_t(1) << 46) |
                              (uint64_t(64) << 32) | (uint64_t(1) << 16);
    return BASE | ((uint64_t)(addr >> 4) & 0x3FFF);
}

__device__ __forceinline__ void cpasync16(uint32_t dst, const void* src) {
    asm volatile("cp.async.cg.shared.global [%0], [%1], 16;" :: "r"(dst), "l"(src));
}

__device__ __forceinline__ void mbar_wait(uint32_t mbar, uint32_t parity) {
    uint32_t done;
    asm volatile("{\n\t.reg .pred p;\n\t"
                 "mbarrier.try_wait.parity.acquire.cta.shared::cta.b64 p, [%1], %2;\n\t"
                 "selp.b32 %0, 1, 0, p;\n\t}"
                 : "=r"(done) : "r"(mbar), "r"(parity) : "memory");
    while (!done) {
        asm volatile("{\n\t.reg .pred p;\n\t"
                     "mbarrier.try_wait.parity.acquire.cta.shared::cta.b64 p, [%1], %2, 0x989680;\n\t"
                     "selp.b32 %0, 1, 0, p;\n\t}"
                     : "=r"(done) : "r"(mbar), "r"(parity) : "memory");
    }
}

#if HAS_TCG
__device__ __forceinline__ void mma_f16(uint32_t d_tmem, uint64_t a_desc, uint64_t b_desc,
                                        uint32_t idesc, uint32_t enable) {
    asm volatile("{\n\t.reg .pred p;\n\tsetp.ne.u32 p, %4, 0;\n\t"
                 "tcgen05.mma.cta_group::1.kind::f16 [%0], %1, %2, %3, {%5, %5, %5, %5}, p;\n\t}"
                 :: "r"(d_tmem), "l"(a_desc), "l"(b_desc), "r"(idesc), "r"(enable), "r"(0u)
                 : "memory");
}

__device__ __forceinline__ void mma_f8(uint32_t d_tmem, uint64_t a_desc, uint64_t b_desc,
                                       uint32_t idesc, uint32_t enable) {
    asm volatile("{\n\t.reg .pred p;\n\tsetp.ne.u32 p, %4, 0;\n\t"
                 "tcgen05.mma.cta_group::1.kind::f8f6f4 [%0], %1, %2, %3, {%5, %5, %5, %5}, p;\n\t}"
                 :: "r"(d_tmem), "l"(a_desc), "l"(b_desc), "r"(idesc), "r"(enable), "r"(0u)
                 : "memory");
}

__device__ __forceinline__ void ldtm_x32(uint32_t* r, uint32_t taddr) {
    asm volatile(
        "tcgen05.ld.sync.aligned.32x32b.x32.b32 "
        "{%0, %1, %2, %3, %4, %5, %6, %7, "
        " %8, %9, %10, %11, %12, %13, %14, %15, "
        " %16, %17, %18, %19, %20, %21, %22, %23, "
        " %24, %25, %26, %27, %28, %29, %30, %31}, [%32];"
        : "=r"(r[0]),  "=r"(r[1]),  "=r"(r[2]),  "=r"(r[3]),
          "=r"(r[4]),  "=r"(r[5]),  "=r"(r[6]),  "=r"(r[7]),
          "=r"(r[8]),  "=r"(r[9]),  "=r"(r[10]), "=r"(r[11]),
          "=r"(r[12]), "=r"(r[13]), "=r"(r[14]), "=r"(r[15]),
          "=r"(r[16]), "=r"(r[17]), "=r"(r[18]), "=r"(r[19]),
          "=r"(r[20]), "=r"(r[21]), "=r"(r[22]), "=r"(r[23]),
          "=r"(r[24]), "=r"(r[25]), "=r"(r[26]), "=r"(r[27]),
          "=r"(r[28]), "=r"(r[29]), "=r"(r[30]), "=r"(r[31])
        : "r"(taddr));
}
#endif  // HAS_TCG

// Load one stage: A tile 256x128B, B tile 256x128B (raw byte blocks).
__device__ __forceinline__ void load_stage(uint32_t smem_base, int s, int kiter,
                                           int m0, int n0, int tid) {
    uint32_t a0 = smem_base + SMEM_A + s * A_STAGE_BYTES;
    uint32_t b0 = smem_base + SMEM_B + s * B_STAGE_BYTES;
    const uint8_t* gA = g_A2 + (size_t)m0 * ROW_BYTES + (size_t)kiter * 128;
    const uint8_t* gB = g_B2 + (size_t)n0 * ROW_BYTES + (size_t)kiter * 128;
#pragma unroll
    for (int i = 0; i < (TILE_M * 8) / 128; i++) {
        int idx = tid + i * 128;
        int row = idx >> 3, c = idx & 7;
        uint32_t off = (uint32_t)row * 128 + c * 16;
        uint32_t sw = off ^ ((off >> 3) & 0x70);
        cpasync16(a0 + sw, gA + (size_t)row * ROW_BYTES + c * 16);
    }
#pragma unroll
    for (int i = 0; i < (TILE_N * 8) / 128; i++) {
        int idx = tid + i * 128;
        int row = idx >> 3, c = idx & 7;
        uint32_t off = (uint32_t)row * 128 + c * 16;
        uint32_t sw = off ^ ((off >> 3) & 0x70);
        cpasync16(b0 + sw, gB + (size_t)row * ROW_BYTES + c * 16);
    }
}

__global__ void __launch_bounds__(128, 1)
gcn_gemm_kernel(float* __restrict__ out) {
#if HAS_TCG
    if (!g_has_tcg) return;
    extern __shared__ char smem[];
    uint32_t smem_base = (smem_u32(smem) + 1023u) & ~1023u;
    int tid = threadIdx.x;
    int wid = tid >> 5;
    int lid = tid & 31;
    int m0 = blockIdx.x * TILE_M;
    int n0 = blockIdx.y * TILE_N;

    if (tid == 0) {
#pragma unroll
        for (int s = 0; s < STAGES; s++) {
            asm volatile("mbarrier.init.shared.b64 [%0], %1;"
                         :: "r"(smem_base + SMEM_MBAR + s * 8), "r"(1u) : "memory");
        }
    }
    if (wid == 0) {
        asm volatile("tcgen05.alloc.cta_group::1.sync.aligned.shared::cta.b32 [%0], %1;"
                     :: "r"(smem_base + SMEM_TMEM_PTR), "r"(512u) : "memory");
    }
    __syncthreads();

    uint32_t tb;
    asm volatile("ld.shared.b32 %0, [%1];" : "=r"(tb) : "r"(smem_base + SMEM_TMEM_PTR));

#pragma unroll
    for (int p = 0; p < STAGES - 1; p++) {
        load_stage(smem_base, p, p, m0, n0, tid);
        asm volatile("cp.async.commit_group;" ::: "memory");
    }

    for (int k = 0; k < K_ITERS; k++) {
        int s = k % STAGES;
        if (k == K_ITERS - 1) {
            asm volatile("cp.async.wait_group 0;" ::: "memory");
        } else {
            asm volatile("cp.async.wait_group 1;" ::: "memory");
        }
        __syncthreads();

        if (wid == 0) {
            if (elect_one()) {
                asm volatile("fence.proxy.async.shared::cta;" ::: "memory");
                uint32_t a_base = smem_base + SMEM_A + s * A_STAGE_BYTES;
                uint32_t b_base = smem_base + SMEM_B + s * B_STAGE_BYTES;
                uint64_t a0d = make_desc(a_base);             // M-half 0
                uint64_t a1d = make_desc(a_base + 128 * 128); // M-half 1
                uint64_t bd  = make_desc(b_base);
                // pass 1: fp16 Ah@Gh, two K16 chunks at byte offsets 0,32 (+0,+2)
#pragma unroll
                for (int ks = 0; ks < 2; ks++) {
                    uint32_t en0 = (k > 0 || ks > 0) ? 1u : 0u;
                    mma_f16(tb,       a0d + 2 * ks, bd + 2 * ks, IDESC_F16, en0);
                    mma_f16(tb + 256, a1d + 2 * ks, bd + 2 * ks, IDESC_F16, en0);
                }
                // pass 2: A(e4m3, +4) @ Gl(e5m2, +6), K32
                mma_f8(tb,       a0d + 4, bd + 6, IDESC_F8(0, 1), 1u);
                mma_f8(tb + 256, a1d + 4, bd + 6, IDESC_F8(0, 1), 1u);
                // pass 3: Al(e5m2, +6) @ G(e4m3, +4), K32
                mma_f8(tb,       a0d + 6, bd + 4, IDESC_F8(1, 0), 1u);
                mma_f8(tb + 256, a1d + 6, bd + 4, IDESC_F8(1, 0), 1u);
                asm volatile(
                    "tcgen05.commit.cta_group::1.mbarrier::arrive::one.shared::cluster.b64 [%0];"
                    :: "r"(smem_base + SMEM_MBAR + s * 8) : "memory");
            }
        }

        int kn = k + STAGES - 1;
        if (kn < K_ITERS) {
            if (k > 0) {
                int t = (k - 1) % STAGES;   // stage to refill; wait MMA of iter k-1
                uint32_t par = (uint32_t)(((k - 1) / STAGES) & 1);
                mbar_wait(smem_base + SMEM_MBAR + t * 8, par);
            }
            load_stage(smem_base, kn % STAGES, kn, m0, n0, tid);
            asm volatile("cp.async.commit_group;" ::: "memory");
        }
    }

    {
        int t = (K_ITERS - 1) % STAGES;
        uint32_t par = (uint32_t)(((K_ITERS - 1) / STAGES) & 1);
        mbar_wait(smem_base + SMEM_MBAR + t * 8, par);
    }
    asm volatile("tcgen05.fence::after_thread_sync;" ::: "memory");

    // Epilogue: TMEM -> regs, scale by dinv[row] * 2^-6 (undo G prescale)
#pragma unroll
    for (int mh = 0; mh < 2; mh++) {
        int row = m0 + mh * 128 + wid * 32 + lid;
        float ds = g_dinv[row] * 0.015625f;
        float* orow = out + (size_t)row * D_FEAT + n0;
#pragma unroll
        for (int c = 0; c < 8; c++) {
            uint32_t r[32];
            ldtm_x32(r, tb + mh * 256 + c * 32);
            asm volatile("tcgen05.wait::ld.sync.aligned;" ::: "memory");
#pragma unroll
            for (int q = 0; q < 8; q++) {
                float4 v;
                v.x = __uint_as_float(r[q * 4 + 0]) * ds;
                v.y = __uint_as_float(r[q * 4 + 1]) * ds;
                v.z = __uint_as_float(r[q * 4 + 2]) * ds;
                v.w = __uint_as_float(r[q * 4 + 3]) * ds;
                *reinterpret_cast<float4*>(orow + c * 32 + q * 4) = v;
            }
        }
    }

    __syncthreads();
    if (wid == 0) {
        asm volatile("tcgen05.relinquish_alloc_permit.cta_group::1.sync.aligned;" ::: "memory");
        asm volatile("tcgen05.dealloc.cta_group::1.sync.aligned.b32 %0, %1;"
                     :: "r"(tb), "r"(512u));
    }
#endif  // HAS_TCG
}

// ---------------------------------------------------------------------------
// FFMA fallback GEMM (only runs if the live device image has no tcgen05).
// ---------------------------------------------------------------------------
__global__ void __launch_bounds__(256)
gcn_gemm_fallback(const float* __restrict__ Mat, const float* __restrict__ F,
                  float* __restrict__ out) {
    if (g_has_tcg) return;
    __shared__ float As[16][132];
    __shared__ float Bs[16][132];
    int m0 = blockIdx.x * 128;
    int n0 = blockIdx.y * 128;
    int tx = threadIdx.x & 15;
    int ty = threadIdx.x >> 4;
    float acc[8][8];
#pragma unroll
    for (int i = 0; i < 8; i++)
#pragma unroll
        for (int j = 0; j < 8; j++) acc[i][j] = 0.f;

    for (int kk = 0; kk < N_NODES; kk += 16) {
        for (int i = threadIdx.x; i < 128 * 16; i += 256) {
            int r = i >> 4, c = i & 15;
            As[c][r] = Mat[(size_t)(m0 + r) * N_NODES + kk + c];
            Bs[c][r] = F[(size_t)(kk + c) * D_FEAT + n0 + r] * g_dinv[kk + c];
        }
        __syncthreads();
#pragma unroll
        for (int c = 0; c < 16; c++) {
            float a[8], b[8];
#pragma unroll
            for (int i = 0; i < 8; i++) a[i] = As[c][ty * 8 + i];
#pragma unroll
            for (int j = 0; j < 8; j++) b[j] = Bs[c][tx * 8 + j];
#pragma unroll
            for (int i = 0; i < 8; i++)
#pragma unroll
                for (int j = 0; j < 8; j++) acc[i][j] += a[i] * b[j];
        }
        __syncthreads();
    }
#pragma unroll
    for (int i = 0; i < 8; i++) {
        int m = m0 + ty * 8 + i;
        float ds = g_dinv[m];
#pragma unroll
        for (int j = 0; j < 8; j++)
            out[(size_t)m * D_FEAT + n0 + tx * 8 + j] = acc[i][j] * ds;
    }
}

// ---------------------------------------------------------------------------
extern "C" void kernel_launch(void* const* d_in, const int* in_sizes, int n_in,
                              void* d_out, int out_size) {
    const float* features = (const float*)d_in[0];
    const float* Mat = (const float*)d_in[1];
    float* out = (float*)d_out;

    rowsum_convert_kernel<<<N_NODES, 256>>>(Mat);

    dim3 tpose_block(32, 8);
    dim3 tpose_grid(D_FEAT / 32, N_NODES / 32);
    scale_transpose_kernel<<<tpose_grid, tpose_block>>>(features);

    cudaFuncSetAttribute(gcn_gemm_kernel, cudaFuncAttributeMaxDynamicSharedMemorySize, SMEM_TOTAL);
    dim3 gemm_grid(N_NODES / TILE_M, D_FEAT / TILE_N);
    gcn_gemm_kernel<<<gemm_grid, 128, SMEM_TOTAL>>>(out);

    dim3 fb_grid(N_NODES / 128, D_FEAT / 128);
    gcn_gemm_fallback<<<fb_grid, 256>>>(Mat, features, out);
}